// round 8
// baseline (speedup 1.0000x reference)
#include <cuda_runtime.h>
#include <math.h>

namespace {
constexpr int Bn = 8, Cn = 4, Hn = 256, Wn = 256;
constexpr int NPIX = Bn * Hn * Wn;      // 524288
constexpr int TPB = 256;
constexpr int NBLK = NPIX / (2 * TPB);  // 1024 (one block == 2 image rows)
}

__device__ double g_acc;      // zero-init at module load; self-reset each run
__device__ unsigned g_count;

__device__ __forceinline__ int deep_vdist(const int* __restrict__ mask, int base,
                                          int h, int w, int c, int is64) {
    int g0 = 512;
    const int lim_u = h, lim_d = Hn - 1 - h;
    const int lim = (lim_u > lim_d) ? lim_u : lim_d;
    bool done = false;
#pragma unroll 1
    for (int kb = 5; kb <= lim && !done; kb += 4) {
        int uu[4], dd[4];
#pragma unroll
        for (int j = 0; j < 4; ++j) {
            int k = kb + j;
            int hu = (k <= lim_u) ? h - k : h;
            int hd = (k <= lim_d) ? h + k : h;
            uu[j] = __ldg(mask + ((base + hu * Wn + w) << is64));
            dd[j] = __ldg(mask + ((base + hd * Wn + w) << is64));
        }
#pragma unroll
        for (int j = 0; j < 4; ++j)
            if (!done && (uu[j] != c || dd[j] != c)) { g0 = kb + j; done = true; }
    }
    return g0;
}

// Exact lower envelope from packed (cls<<20|g0^2) row; body runs only when m>1.
__device__ __forceinline__ float envelope(const int* __restrict__ sp, int w,
                                          int c, float m) {
#pragma unroll 1
    for (int r = 1; r < Wn; ++r) {
        float r2 = (float)(r * r);
        if (r2 >= m) break;                   // remaining candidates >= r^2 >= m
        int xl = w - r, xr = w + r;
        if (xl < 0 && xr >= Wn) break;
        if (xl >= 0) {
            int pk = sp[xl];
            float g = ((pk >> 20) == c) ? (float)(pk & 0xFFFFF) : 0.0f;
            m = fminf(m, g + r2);
        }
        if (xr < Wn) {
            int pk = sp[xr];
            float g = ((pk >> 20) == c) ? (float)(pk & 0xFFFFF) : 0.0f;
            m = fminf(m, g + r2);
        }
    }
    return m;
}

__global__ __launch_bounds__(TPB, 8)
void boundary_loss_kernel(const float* __restrict__ pred,
                          const int* __restrict__ mask,
                          float* __restrict__ out, int out_n) {
    __shared__ int s_pk[2][Wn];   // (class << 20) | g0^2  per row pixel
    __shared__ float ws[TPB / 32];

    const int lane = threadIdx.x & 31;
    const int w = threadIdx.x;                 // TPB == Wn
    const int b = blockIdx.x >> 7;             // 128 row-pairs per image
    const int hA = (blockIdx.x & 127) * 2;
    const int hB = hA + 1;
    const int base = b * (Hn * Wn);
    const bool interior = (hA >= 4) && (hA <= Hn - 6);  // rows hA-4..hB+4 in range

    // ---- one MLP round: is64 probe + 10-row mask window ----
    const int probe = __ldg(mask + 2 * lane + 1);
    int arr[10];                               // rows hA-4 .. hA+5
    if (interior) {
        const int a0 = base + (hA - 4) * Wn + w;
#pragma unroll
        for (int i = 0; i < 10; ++i) arr[i] = __ldg(mask + a0 + i * Wn);
    } else {
#pragma unroll
        for (int i = 0; i < 10; ++i) {
            int hr = hA - 4 + i;
            hr = (hr < 0) ? 0 : ((hr > Hn - 1) ? Hn - 1 : hr);
            arr[i] = __ldg(mask + base + hr * Wn + w);
        }
    }
    // int64 storage => all odd 32-bit words zero (fp prob 4^-32): reload.
    const int is64 = __all_sync(0xFFFFFFFFu, probe == 0) ? 1 : 0;
    if (is64) {
#pragma unroll
        for (int i = 0; i < 10; ++i) {
            int hr = hA - 4 + i;
            hr = (hr < 0) ? 0 : ((hr > Hn - 1) ? Hn - 1 : hr);
            arr[i] = __ldg(mask + 2 * (base + hr * Wn + w));
        }
    }
    const int cA = arr[4];
    const int cB = arr[5];

    // class-directed pred loads (consumed last; latency hides under envelope)
    const int ppix = b * Cn * Hn * Wn + w;
    float pA = 0.0f, pB = 0.0f;
    if (cA != 0) pA = __ldg(pred + ppix + (cA * Hn + hA) * Wn);
    if (cB != 0) pB = __ldg(pred + ppix + (cB * Hn + hB) * Wn);

    // ---- vertical distances from the window (k<=4), rare deep fallback ----
    float g2A = 0.0f, g2B = 0.0f;
    int pkA = 0, pkB = 0;
    if (cA != 0) {
        int bits = 0;
        if (interior) {
#pragma unroll
            for (int j = 1; j <= 4; ++j)
                bits |= ((arr[4 - j] != cA) | (arr[4 + j] != cA)) << (j - 1);
        } else {
#pragma unroll
            for (int j = 1; j <= 4; ++j) {
                int uv = (j <= hA) ? arr[4 - j] : cA;
                int dv = (hA + j < Hn) ? arr[4 + j] : cA;
                bits |= ((uv != cA) | (dv != cA)) << (j - 1);
            }
        }
        int g0 = bits ? __ffs(bits) : deep_vdist(mask, base, hA, w, cA, is64);
        int gg = g0 * g0;
        g2A = (float)gg;
        pkA = (cA << 20) | gg;
    }
    if (cB != 0) {
        int bits = 0;
        if (interior) {
#pragma unroll
            for (int j = 1; j <= 4; ++j)
                bits |= ((arr[5 - j] != cB) | (arr[5 + j] != cB)) << (j - 1);
        } else {
#pragma unroll
            for (int j = 1; j <= 4; ++j) {
                int uv = (j <= hB) ? arr[5 - j] : cB;
                int dv = (hB + j < Hn) ? arr[5 + j] : cB;
                bits |= ((uv != cB) | (dv != cB)) << (j - 1);
            }
        }
        int g0 = bits ? __ffs(bits) : deep_vdist(mask, base, hB, w, cB, is64);
        int gg = g0 * g0;
        g2B = (float)gg;
        pkB = (cB << 20) | gg;
    }

    s_pk[0][w] = pkA;
    s_pk[1][w] = pkB;
    __syncthreads();

    // ---- exact horizontal lower envelopes (body skipped when m == 1) ----
    const float norm = (float)(sqrt((double)(Hn * Hn + Wn * Wn)) + 1e-6);
    float term = 0.0f;
    if (cA != 0) {
        float m = envelope(s_pk[0], w, cA, g2A);
        term += pA * (sqrtf(m) / norm);
    }
    if (cB != 0) {
        float m = envelope(s_pk[1], w, cB, g2B);
        term += pB * (sqrtf(m) / norm);
    }

    // ---- block reduction + last-block finalize ----
#pragma unroll
    for (int o = 16; o > 0; o >>= 1)
        term += __shfl_down_sync(0xFFFFFFFFu, term, o);
    if (lane == 0) ws[threadIdx.x >> 5] = term;
    __syncthreads();
    if (threadIdx.x < TPB / 32) {
        float v = ws[threadIdx.x];
#pragma unroll
        for (int o = 4; o > 0; o >>= 1)
            v += __shfl_down_sync(0xFFu, v, o);
        if (threadIdx.x == 0) {
            atomicAdd(&g_acc, (double)v);
            __threadfence();  // order my g_acc add before my g_count bump
            unsigned prev = atomicAdd(&g_count, 1u);
            if (prev == (unsigned)(gridDim.x - 1)) {
                double total = atomicAdd(&g_acc, 0.0);  // L2-coherent read
                float r = (float)(total / ((double)NPIX * (Cn - 1)));
                for (int i = 0; i < out_n; ++i) out[i] = r;
                g_acc = 0.0;   // reset for next graph replay (deterministic)
                g_count = 0u;
            }
        }
    }
}

extern "C" void kernel_launch(void* const* d_in, const int* in_sizes, int n_in,
                              void* d_out, int out_size) {
    const float* pred;
    const int* mask;
    if (in_sizes[0] >= in_sizes[1]) {
        pred = (const float*)d_in[0];
        mask = (const int*)d_in[1];
    } else {
        pred = (const float*)d_in[1];
        mask = (const int*)d_in[0];
    }
    boundary_loss_kernel<<<NBLK, TPB>>>(pred, mask, (float*)d_out, out_size);
}